// round 11
// baseline (speedup 1.0000x reference)
#include <cuda_runtime.h>
#include <cuda_bf16.h>
#include <mma.h>
#include <math.h>
#include <stdint.h>

using namespace nvcuda;

#define BB 4
#define TT 2048
#define DD 1024
#define HH 16
#define DH 64
#define MTOT (BB*TT)            // 8192
#define OUT0 (BB*TT*DD)
#define KDIM 1024
#define NQKV 3072

// ---------------- scratch ---------------------------------------------------
__device__ float g_q[BB*HH*TT*DH];
__device__ float g_k[BB*HH*TT*DH];
__device__ float g_v[BB*HH*TT*DH];
__device__ float g_ctx[MTOT*DD];
__device__ __nv_bfloat16 g_xhi[MTOT*KDIM],    g_xlo[MTOT*KDIM];
__device__ __nv_bfloat16 g_wqT_hi[NQKV*KDIM], g_wqT_lo[NQKV*KDIM];
__device__ __nv_bfloat16 g_woT_hi[DD*KDIM],   g_woT_lo[DD*KDIM];
__device__ __nv_bfloat16 g_ctx_hi[MTOT*DD],   g_ctx_lo[MTOT*DD];
__device__ int g_flag1;   // 1 => bf16 QKV GEMM wrong/absent -> fp32 fallback
__device__ int g_flag2;   // 1 => bf16 out-proj wrong/absent -> fp32 fallback

__global__ void reset_flags() { g_flag1 = 0; g_flag2 = 0; }

// ---------------- prep kernels ---------------------------------------------
__global__ __launch_bounds__(256)
void conv_split_k(const float* __restrict__ src, __nv_bfloat16* __restrict__ hi,
                  __nv_bfloat16* __restrict__ lo, int n4) {
    int i = blockIdx.x * blockDim.x + threadIdx.x;
    if (i >= n4) return;
    float4 v = reinterpret_cast<const float4*>(src)[i];
    __nv_bfloat16 h0 = __float2bfloat16(v.x), h1 = __float2bfloat16(v.y);
    __nv_bfloat16 h2 = __float2bfloat16(v.z), h3 = __float2bfloat16(v.w);
    __nv_bfloat16 l0 = __float2bfloat16(v.x - __bfloat162float(h0));
    __nv_bfloat16 l1 = __float2bfloat16(v.y - __bfloat162float(h1));
    __nv_bfloat16 l2 = __float2bfloat16(v.z - __bfloat162float(h2));
    __nv_bfloat16 l3 = __float2bfloat16(v.w - __bfloat162float(h3));
    reinterpret_cast<__nv_bfloat162*>(hi)[i * 2 + 0] = __halves2bfloat162(h0, h1);
    reinterpret_cast<__nv_bfloat162*>(hi)[i * 2 + 1] = __halves2bfloat162(h2, h3);
    reinterpret_cast<__nv_bfloat162*>(lo)[i * 2 + 0] = __halves2bfloat162(l0, l1);
    reinterpret_cast<__nv_bfloat162*>(lo)[i * 2 + 1] = __halves2bfloat162(l2, l3);
}

__global__ __launch_bounds__(256)
void transpose_split_k(const float* __restrict__ src, __nv_bfloat16* __restrict__ hi,
                       __nv_bfloat16* __restrict__ lo, int K, int N) {
    __shared__ float t[32][33];
    int n0 = blockIdx.x * 32, k0 = blockIdx.y * 32;
    int tx = threadIdx.x, ty = threadIdx.y;
    #pragma unroll
    for (int i = 0; i < 4; i++)
        t[ty + 8 * i][tx] = src[(size_t)(k0 + ty + 8 * i) * N + n0 + tx];
    __syncthreads();
    #pragma unroll
    for (int i = 0; i < 4; i++) {
        float v = t[tx][ty + 8 * i];
        size_t idx = (size_t)(n0 + ty + 8 * i) * K + k0 + tx;
        __nv_bfloat16 h = __float2bfloat16(v);
        hi[idx] = h;
        lo[idx] = __float2bfloat16(v - __bfloat162float(h));
    }
}

// ---------------- WMMA split-bf16 GEMM (R5 structure + register prefetch) ---
#define CHUNK 32
#define NCH (KDIM/CHUNK)            // 32
#define PITCH 48                    // bf16 elems per smem row (96B, 32B-aligned)
#define PITCH_B 96
#define MAT_BYTES (128*PITCH_B)     // 12288
#define EPI_PITCH 136               // floats (544B rows)
#define GEMM2_SMEM (128*EPI_PITCH*4)  // 69632 >= 4*MAT_BYTES (49152)

template<int MODE>   // 1: QKV scatter epilogue, 0: plain C epilogue
__global__ __launch_bounds__(256)
void tc_gemm2(const __nv_bfloat16* __restrict__ Ahi, const __nv_bfloat16* __restrict__ Alo,
              const __nv_bfloat16* __restrict__ Bhi, const __nv_bfloat16* __restrict__ Blo,
              const float* __restrict__ bias, float* __restrict__ C, int N) {
    extern __shared__ char smem[];
    const int tid = threadIdx.x;
    const int wid = tid >> 5;
    const int wm = wid & 3, wn = wid >> 2;
    const int m0 = blockIdx.y * 128, n0 = blockIdx.x * 128;

    wmma::fragment<wmma::accumulator, 16, 16, 16, float> acc[2][4];
    #pragma unroll
    for (int mt = 0; mt < 2; mt++)
        #pragma unroll
        for (int nt = 0; nt < 4; nt++)
            wmma::fill_fragment(acc[mt][nt], 0.0f);

    // fixed per-thread load slots
    const __nv_bfloat16* gptr[8];
    uint32_t ssto[8];
    #pragma unroll
    for (int j = 0; j < 8; j++) {
        int idx = j * 256 + tid;
        int mat = idx >> 9;
        int r   = (idx >> 2) & 127;
        int c4  = idx & 3;
        const __nv_bfloat16* gp = (mat == 0) ? Ahi : (mat == 1) ? Alo
                                 : (mat == 2) ? Bhi : Blo;
        int grow = ((mat < 2) ? m0 : n0) + r;
        gptr[j] = gp + (size_t)grow * KDIM + c4 * 8;
        ssto[j] = mat * MAT_BYTES + r * PITCH_B + c4 * 16;
    }

    uint4 rg[8];
    #pragma unroll
    for (int j = 0; j < 8; j++)
        rg[j] = *reinterpret_cast<const uint4*>(gptr[j]);   // chunk 0

    for (int ch = 0; ch < NCH; ch++) {
        __syncthreads();   // previous compute done before smem overwrite
        #pragma unroll
        for (int j = 0; j < 8; j++)
            *reinterpret_cast<uint4*>(smem + ssto[j]) = rg[j];
        __syncthreads();

        if (ch + 1 < NCH) {
            const int kof = (ch + 1) * CHUNK;
            #pragma unroll
            for (int j = 0; j < 8; j++)
                rg[j] = *reinterpret_cast<const uint4*>(gptr[j] + kof);
        }

        const __nv_bfloat16* aHi = reinterpret_cast<const __nv_bfloat16*>(smem);
        const __nv_bfloat16* aLo = reinterpret_cast<const __nv_bfloat16*>(smem + MAT_BYTES);
        const __nv_bfloat16* bHi = reinterpret_cast<const __nv_bfloat16*>(smem + 2 * MAT_BYTES);
        const __nv_bfloat16* bLo = reinterpret_cast<const __nv_bfloat16*>(smem + 3 * MAT_BYTES);

        #pragma unroll
        for (int ks = 0; ks < 2; ks++) {
            const int kk = ks * 16;
            wmma::fragment<wmma::matrix_a, 16, 16, 16, __nv_bfloat16, wmma::row_major> fa_hi[2], fa_lo[2];
            #pragma unroll
            for (int mt = 0; mt < 2; mt++) {
                const int ar = wm * 32 + mt * 16;
                wmma::load_matrix_sync(fa_hi[mt], aHi + ar * PITCH + kk, PITCH);
                wmma::load_matrix_sync(fa_lo[mt], aLo + ar * PITCH + kk, PITCH);
            }
            #pragma unroll
            for (int nt = 0; nt < 4; nt++) {
                const int br = wn * 64 + nt * 16;
                wmma::fragment<wmma::matrix_b, 16, 16, 16, __nv_bfloat16, wmma::col_major> fb_hi, fb_lo;
                wmma::load_matrix_sync(fb_hi, bHi + br * PITCH + kk, PITCH);
                wmma::load_matrix_sync(fb_lo, bLo + br * PITCH + kk, PITCH);
                #pragma unroll
                for (int mt = 0; mt < 2; mt++) {
                    wmma::mma_sync(acc[mt][nt], fa_hi[mt], fb_hi, acc[mt][nt]);
                    wmma::mma_sync(acc[mt][nt], fa_hi[mt], fb_lo, acc[mt][nt]);
                    wmma::mma_sync(acc[mt][nt], fa_lo[mt], fb_hi, acc[mt][nt]);
                }
            }
        }
    }
    __syncthreads();

    // epilogue: frags -> smem staging -> bias + store/scatter
    float* epi = reinterpret_cast<float*>(smem);
    #pragma unroll
    for (int mt = 0; mt < 2; mt++)
        #pragma unroll
        for (int nt = 0; nt < 4; nt++)
            wmma::store_matrix_sync(&epi[(wm * 32 + mt * 16) * EPI_PITCH + wn * 64 + nt * 16],
                                    acc[mt][nt], EPI_PITCH, wmma::mem_row_major);
    __syncthreads();

    const int row = tid >> 1, half = tid & 1;
    const float* src = &epi[row * EPI_PITCH + half * 64];
    if (MODE == 1) {
        const int n_base = n0 + half * 64;
        const int which = n_base >> 10;
        const int h = (n_base & 1023) >> 6;
        const int bb = (m0 + row) >> 11;
        const int t = (m0 + row) & 2047;
        float* dst = (which == 0 ? g_q : which == 1 ? g_k : g_v) +
                     (((size_t)(bb * HH + h)) * TT + t) * DH;
        const float* bp = bias + n_base;
        #pragma unroll
        for (int j = 0; j < 16; j++) {
            float4 v = *reinterpret_cast<const float4*>(src + j * 4);
            float4 bv = *reinterpret_cast<const float4*>(bp + j * 4);
            v.x += bv.x; v.y += bv.y; v.z += bv.z; v.w += bv.w;
            *reinterpret_cast<float4*>(dst + j * 4) = v;
        }
    } else {
        float* dst = C + (size_t)(m0 + row) * N + n0 + half * 64;
        const float* bp = bias + n0 + half * 64;
        #pragma unroll
        for (int j = 0; j < 16; j++) {
            float4 v = *reinterpret_cast<const float4*>(src + j * 4);
            float4 bv = *reinterpret_cast<const float4*>(bp + j * 4);
            v.x += bv.x; v.y += bv.y; v.z += bv.z; v.w += bv.w;
            *reinterpret_cast<float4*>(dst + j * 4) = v;
        }
    }
}

// ---------------- cheap parallel checkers (256 blocks x 256 threads) --------
__global__ __launch_bounds__(256)
void check_qkv(const float* __restrict__ x, const float* __restrict__ w,
               const float* __restrict__ b) {
    __shared__ float red[256];
    const int s = blockIdx.x;
    const int m = (s * 131) & 8191;
    const int n = (s * 97) % 3072;
    float p = 0.f;
    for (int k = threadIdx.x; k < KDIM; k += 256)
        p += x[(size_t)m * KDIM + k] * w[(size_t)k * NQKV + n];
    red[threadIdx.x] = p;
    __syncthreads();
    #pragma unroll
    for (int o = 128; o; o >>= 1) {
        if (threadIdx.x < o) red[threadIdx.x] += red[threadIdx.x + o];
        __syncthreads();
    }
    if (threadIdx.x == 0) {
        float ref = red[0] + b[n];
        const int which = n >> 10, rem = n & 1023;
        const int h = rem >> 6, dh = rem & 63;
        const int bb = m >> 11, tt = m & 2047;
        const float* dst = (which == 0 ? g_q : which == 1 ? g_k : g_v);
        float val = dst[(((size_t)(bb * HH + h)) * TT + tt) * DH + dh];
        if (fabsf(val - ref) > 1e-2f * (1.0f + fabsf(ref))) atomicOr(&g_flag1, 1);
    }
}

__global__ __launch_bounds__(256)
void check_out(const float* __restrict__ w, const float* __restrict__ b,
               const float* __restrict__ out) {
    __shared__ float red[256];
    const int s = blockIdx.x;
    const int m = (s * 131) & 8191;
    const int n = (s * 61) & 1023;
    float p = 0.f;
    for (int k = threadIdx.x; k < KDIM; k += 256)
        p += g_ctx[(size_t)m * DD + k] * w[(size_t)k * DD + n];
    red[threadIdx.x] = p;
    __syncthreads();
    #pragma unroll
    for (int o = 128; o; o >>= 1) {
        if (threadIdx.x < o) red[threadIdx.x] += red[threadIdx.x + o];
        __syncthreads();
    }
    if (threadIdx.x == 0) {
        float ref = red[0] + b[n];
        float val = out[(size_t)m * DD + n];
        if (fabsf(val - ref) > 1e-2f * (1.0f + fabsf(ref))) atomicOr(&g_flag2, 1);
    }
}

// ---------------- fp32 SGEMM fallback (R8 prefetch version, flag-guarded) ---
template<int MODE>
__global__ __launch_bounds__(256)
void sgemm_k(const float* __restrict__ Ain, const float* __restrict__ Bw,
             const float* __restrict__ bias, float* __restrict__ C,
             int M, int N, int K) {
    if (*(volatile int*)((MODE == 1) ? &g_flag1 : &g_flag2) == 0) return;
    __shared__ float As[16][132];
    __shared__ float Bs[16][132];

    const float* A = (MODE == 0) ? g_ctx : Ain;
    const int tid = threadIdx.x;
    const int tx = tid & 15, ty = tid >> 4;
    const int m0 = blockIdx.y * 128, n0 = blockIdx.x * 128;

    const int arow0 = (tid + 0) >> 2,        ac0 = ((tid + 0) & 3) * 4;
    const int arow1 = (tid + 256) >> 2,      ac1 = ((tid + 256) & 3) * 4;
    const int brow0 = (tid + 0) >> 5,        bc0 = ((tid + 0) & 31) * 4;
    const int brow1 = (tid + 256) >> 5,      bc1 = ((tid + 256) & 31) * 4;

    float acc[8][8];
    #pragma unroll
    for (int i = 0; i < 8; i++)
        #pragma unroll
        for (int j = 0; j < 8; j++) acc[i][j] = 0.f;

    float4 pa0 = *reinterpret_cast<const float4*>(&A[(size_t)(m0 + arow0) * K + ac0]);
    float4 pa1 = *reinterpret_cast<const float4*>(&A[(size_t)(m0 + arow1) * K + ac1]);
    float4 pb0 = *reinterpret_cast<const float4*>(&Bw[(size_t)brow0 * N + n0 + bc0]);
    float4 pb1 = *reinterpret_cast<const float4*>(&Bw[(size_t)brow1 * N + n0 + bc1]);

    for (int k0 = 0; k0 < K; k0 += 16) {
        As[ac0 + 0][arow0] = pa0.x; As[ac0 + 1][arow0] = pa0.y;
        As[ac0 + 2][arow0] = pa0.z; As[ac0 + 3][arow0] = pa0.w;
        As[ac1 + 0][arow1] = pa1.x; As[ac1 + 1][arow1] = pa1.y;
        As[ac1 + 2][arow1] = pa1.z; As[ac1 + 3][arow1] = pa1.w;
        *reinterpret_cast<float4*>(&Bs[brow0][bc0]) = pb0;
        *reinterpret_cast<float4*>(&Bs[brow1][bc1]) = pb1;
        __syncthreads();

        if (k0 + 16 < K) {
            pa0 = *reinterpret_cast<const float4*>(&A[(size_t)(m0 + arow0) * K + k0 + 16 + ac0]);
            pa1 = *reinterpret_cast<const float4*>(&A[(size_t)(m0 + arow1) * K + k0 + 16 + ac1]);
            pb0 = *reinterpret_cast<const float4*>(&Bw[(size_t)(k0 + 16 + brow0) * N + n0 + bc0]);
            pb1 = *reinterpret_cast<const float4*>(&Bw[(size_t)(k0 + 16 + brow1) * N + n0 + bc1]);
        }

        #pragma unroll
        for (int kk = 0; kk < 16; kk++) {
            float a[8], bfr[8];
            *reinterpret_cast<float4*>(&a[0]) = *reinterpret_cast<float4*>(&As[kk][ty * 8]);
            *reinterpret_cast<float4*>(&a[4]) = *reinterpret_cast<float4*>(&As[kk][ty * 8 + 4]);
            *reinterpret_cast<float4*>(&bfr[0]) = *reinterpret_cast<float4*>(&Bs[kk][tx * 8]);
            *reinterpret_cast<float4*>(&bfr[4]) = *reinterpret_cast<float4*>(&Bs[kk][tx * 8 + 4]);
            #pragma unroll
            for (int i = 0; i < 8; i++)
                #pragma unroll
                for (int j = 0; j < 8; j++) acc[i][j] += a[i] * bfr[j];
        }
        __syncthreads();
    }

    if (MODE == 0) {
        #pragma unroll
        for (int i = 0; i < 8; i++) {
            int row = m0 + ty * 8 + i;
            #pragma unroll
            for (int j0 = 0; j0 < 8; j0 += 4) {
                int col = n0 + tx * 8 + j0;
                float4 v;
                v.x = acc[i][j0 + 0] + bias[col + 0];
                v.y = acc[i][j0 + 1] + bias[col + 1];
                v.z = acc[i][j0 + 2] + bias[col + 2];
                v.w = acc[i][j0 + 3] + bias[col + 3];
                *reinterpret_cast<float4*>(&C[(size_t)row * N + col]) = v;
            }
        }
    } else {
        #pragma unroll
        for (int i = 0; i < 8; i++) {
            int row = m0 + ty * 8 + i;
            int bb = row >> 11, t = row & 2047;
            #pragma unroll
            for (int j = 0; j < 8; j++) {
                int n = n0 + tx * 8 + j;
                int which = n >> 10;
                int rem = n & 1023;
                int h = rem >> 6, dh = rem & 63;
                float v = acc[i][j] + bias[n];
                float* dst = (which == 0) ? g_q : (which == 1) ? g_k : g_v;
                dst[(((size_t)(bb * HH + h)) * TT + t) * DH + dh] = v;
            }
        }
    }
}

// ---------------------------------------------------------------------------
// Attention (R8, known-good; emits fp32 ctx + bf16 hi/lo ctx)
// ---------------------------------------------------------------------------
#define SM_QS   0
#define SM_KT   1024
#define SM_VB   (1024 + 8192)
#define SM_SS   (1024 + 8192 + 8704)
#define ATTN_SMEM_FLOATS (1024 + 8192 + 8704 + 32768)
#define ATTN_SMEM_BYTES  (ATTN_SMEM_FLOATS * 4)

__global__ __launch_bounds__(256)
void attn_kernel(float* __restrict__ wout) {
    extern __shared__ float sm[];
    float* qs = sm + SM_QS;
    float* kT = sm + SM_KT;
    float* vb = sm + SM_VB;
    float* sS = sm + SM_SS;

    const int tid = threadIdx.x;
    const int qt = blockIdx.x, h = blockIdx.y, b = blockIdx.z;
    const int q0 = qt * 16;
    const size_t hb = ((size_t)(b * HH + h)) * TT;

    {
        int r = tid >> 4, c = (tid & 15) * 4;
        float4 v = *reinterpret_cast<const float4*>(&g_q[(hb + q0 + r) * DH + c]);
        qs[r * 64 + c + 0] = v.x * 0.125f;
        qs[r * 64 + c + 1] = v.y * 0.125f;
        qs[r * 64 + c + 2] = v.z * 0.125f;
        qs[r * 64 + c + 3] = v.w * 0.125f;
    }

    const int nch = (q0 + 16 + 127) >> 7;
    const int Lc = nch << 7;

    {
        const int rg = tid >> 5;
        const int cg = tid & 31;
        for (int c = 0; c < nch; c++) {
            const int kb = c << 7;
            __syncthreads();
            #pragma unroll
            for (int i = 0; i < 2; i++) {
                int gid = tid + i * 256;
                int kq = gid >> 4, c4 = gid & 15;
                float vr[4][4];
                #pragma unroll
                for (int jj = 0; jj < 4; jj++) {
                    float4 t4 = *reinterpret_cast<const float4*>(
                        &g_k[(hb + kb + kq * 4 + jj) * DH + c4 * 4]);
                    vr[jj][0] = t4.x; vr[jj][1] = t4.y;
                    vr[jj][2] = t4.z; vr[jj][3] = t4.w;
                }
                #pragma unroll
                for (int dd = 0; dd < 4; dd++) {
                    int row = c4 * 4 + dd;
                    int p = kq ^ (row & 31);
                    *reinterpret_cast<float4*>(&kT[row * 128 + p * 4]) =
                        make_float4(vr[0][dd], vr[1][dd], vr[2][dd], vr[3][dd]);
                }
            }
            __syncthreads();
            float acc[2][4];
            #pragma unroll
            for (int i = 0; i < 2; i++)
                #pragma unroll
                for (int j = 0; j < 4; j++) acc[i][j] = 0.f;
            #pragma unroll
            for (int kk = 0; kk < 64; kk++) {
                float qa = qs[(rg * 2 + 0) * 64 + kk];
                float qb = qs[(rg * 2 + 1) * 64 + kk];
                float4 kv = *reinterpret_cast<const float4*>(
                    &kT[kk * 128 + (cg ^ (kk & 31)) * 4]);
                acc[0][0] += qa * kv.x; acc[0][1] += qa * kv.y;
                acc[0][2] += qa * kv.z; acc[0][3] += qa * kv.w;
                acc[1][0] += qb * kv.x; acc[1][1] += qb * kv.y;
                acc[1][2] += qb * kv.z; acc[1][3] += qb * kv.w;
            }
            #pragma unroll
            for (int i = 0; i < 2; i++) {
                int row = rg * 2 + i;
                int qg = q0 + row;
                int kbase = kb + cg * 4;
                float4 o;
                o.x = (kbase + 0 <= qg) ? acc[i][0] : -1e30f;
                o.y = (kbase + 1 <= qg) ? acc[i][1] : -1e30f;
                o.z = (kbase + 2 <= qg) ? acc[i][2] : -1e30f;
                o.w = (kbase + 3 <= qg) ? acc[i][3] : -1e30f;
                *reinterpret_cast<float4*>(&sS[row * 2048 + kbase]) = o;
            }
        }
    }
    __syncthreads();

    {
        const int warp = tid >> 5, lane = tid & 31;
        for (int i = warp; i < 16; i += 8) {
            float* row = &sS[i * 2048];
            float mx = -1e30f;
            for (int j = lane; j < Lc; j += 32) mx = fmaxf(mx, row[j]);
            #pragma unroll
            for (int o = 16; o; o >>= 1) mx = fmaxf(mx, __shfl_xor_sync(0xffffffffu, mx, o));
            float s = 0.f;
            for (int j = lane; j < Lc; j += 32) {
                float e = __expf(row[j] - mx);
                row[j] = e; s += e;
            }
            #pragma unroll
            for (int o = 16; o; o >>= 1) s += __shfl_xor_sync(0xffffffffu, s, o);
            float inv = 1.0f / s;
            float* wr = &wout[(hb + q0 + i) * TT];
            for (int j = lane; j < Lc; j += 32) {
                float w = row[j] * inv;
                row[j] = w;
                wr[j] = w;
            }
            for (int j = Lc + lane; j < TT; j += 32) wr[j] = 0.f;
        }
    }
    __syncthreads();

    {
        const int r = tid >> 4, dg = tid & 15;
        float a0 = 0.f, a1 = 0.f, a2 = 0.f, a3 = 0.f;
        for (int c = 0; c < nch; c++) {
            const int kb = c << 7;
            __syncthreads();
            #pragma unroll
            for (int i = 0; i < 8; i++) {
                int idx = tid + i * 256;
                int key = idx >> 4, c4 = (idx & 15) * 4;
                *reinterpret_cast<float4*>(&vb[key * 68 + c4]) =
                    *reinterpret_cast<const float4*>(
                        &g_v[(hb + kb + key) * DH + c4]);
            }
            __syncthreads();
            #pragma unroll 4
            for (int j = 0; j < 128; j++) {
                float w = sS[r * 2048 + kb + j];
                float4 v4 = *reinterpret_cast<const float4*>(&vb[j * 68 + dg * 4]);
                a0 += w * v4.x; a1 += w * v4.y; a2 += w * v4.z; a3 += w * v4.w;
            }
        }
        size_t cidx = ((size_t)(b * TT + q0 + r)) * DD + h * 64 + dg * 4;
        *reinterpret_cast<float4*>(&g_ctx[cidx]) = make_float4(a0, a1, a2, a3);
        __nv_bfloat16 h0 = __float2bfloat16(a0), h1 = __float2bfloat16(a1);
        __nv_bfloat16 h2 = __float2bfloat16(a2), h3 = __float2bfloat16(a3);
        __nv_bfloat16 l0 = __float2bfloat16(a0 - __bfloat162float(h0));
        __nv_bfloat16 l1 = __float2bfloat16(a1 - __bfloat162float(h1));
        __nv_bfloat16 l2 = __float2bfloat16(a2 - __bfloat162float(h2));
        __nv_bfloat16 l3 = __float2bfloat16(a3 - __bfloat162float(h3));
        *reinterpret_cast<__nv_bfloat162*>(&g_ctx_hi[cidx])     = __halves2bfloat162(h0, h1);
        *reinterpret_cast<__nv_bfloat162*>(&g_ctx_hi[cidx + 2]) = __halves2bfloat162(h2, h3);
        *reinterpret_cast<__nv_bfloat162*>(&g_ctx_lo[cidx])     = __halves2bfloat162(l0, l1);
        *reinterpret_cast<__nv_bfloat162*>(&g_ctx_lo[cidx + 2]) = __halves2bfloat162(l2, l3);
    }
}

// ---------------------------------------------------------------------------
extern "C" void kernel_launch(void* const* d_in, const int* in_sizes, int n_in,
                              void* d_out, int out_size) {
    const float* x     = (const float*)d_in[0];
    const float* w_qkv = (const float*)d_in[1];
    const float* b_qkv = (const float*)d_in[2];
    const float* w_out = (const float*)d_in[3];
    const float* b_out = (const float*)d_in[4];
    float* out     = (float*)d_out;
    float* weights = out + OUT0;
    (void)in_sizes; (void)n_in; (void)out_size;

    cudaFuncSetAttribute(attn_kernel, cudaFuncAttributeMaxDynamicSharedMemorySize,
                         ATTN_SMEM_BYTES);
    cudaFuncSetAttribute(tc_gemm2<1>, cudaFuncAttributeMaxDynamicSharedMemorySize,
                         GEMM2_SMEM);
    cudaFuncSetAttribute(tc_gemm2<0>, cudaFuncAttributeMaxDynamicSharedMemorySize,
                         GEMM2_SMEM);

    reset_flags<<<1, 1>>>();

    // prep: split x, transpose+split weights
    conv_split_k<<<(MTOT * KDIM / 4 + 255) / 256, 256>>>(x, g_xhi, g_xlo, MTOT * KDIM / 4);
    transpose_split_k<<<dim3(NQKV / 32, KDIM / 32), dim3(32, 8)>>>(
        w_qkv, g_wqT_hi, g_wqT_lo, KDIM, NQKV);
    transpose_split_k<<<dim3(DD / 32, KDIM / 32), dim3(32, 8)>>>(
        w_out, g_woT_hi, g_woT_lo, KDIM, DD);

    // 1) QKV: bf16 wmma (prefetch-pipelined) -> checker -> guarded fallback
    tc_gemm2<1><<<dim3(NQKV / 128, MTOT / 128), 256, GEMM2_SMEM>>>(
        g_xhi, g_xlo, g_wqT_hi, g_wqT_lo, b_qkv, nullptr, NQKV);
    check_qkv<<<256, 256>>>(x, w_qkv, b_qkv);
    sgemm_k<1><<<dim3(NQKV / 128, MTOT / 128), 256>>>(
        x, w_qkv, b_qkv, nullptr, MTOT, NQKV, KDIM);

    // 2) causal attention
    attn_kernel<<<dim3(TT / 16, HH, BB), 256, ATTN_SMEM_BYTES>>>(weights);

    // 3) out-proj: bf16 wmma -> checker -> guarded fallback
    tc_gemm2<0><<<dim3(DD / 128, MTOT / 128), 256, GEMM2_SMEM>>>(
        g_ctx_hi, g_ctx_lo, g_woT_hi, g_woT_lo, b_out, out, DD);
    check_out<<<256, 256>>>(w_out, b_out, out);
    sgemm_k<0><<<dim3(DD / 128, MTOT / 128), 256>>>(
        nullptr, w_out, b_out, out, MTOT, DD, KDIM);
}

// round 12
// speedup vs baseline: 3.4858x; 3.4858x over previous
#include <cuda_runtime.h>
#include <cuda_bf16.h>
#include <math.h>

#define BB 4
#define TT 2048
#define DD 1024
#define HH 16
#define DH 64
#define MTOT (BB*TT)            // 8192
#define OUT0 (BB*TT*DD)         // 8388608 floats: "out" part of d_out

// Scratch (static device arrays; runtime alloc forbidden)
__device__ float g_q[BB*HH*TT*DH];
__device__ float g_k[BB*HH*TT*DH];
__device__ float g_v[BB*HH*TT*DH];
__device__ float g_ctx[BB*TT*DD];

// ---------------------------------------------------------------------------
// SGEMM: C[M,N] = A[M,K] @ B[K,N] + bias
// Register prefetch + double-buffered smem (one barrier per K-slice),
// __launch_bounds__(256, 2) pins regs <= 128 so 2 blocks/SM survive.
// MODE 0: A = g_ctx, plain row-major epilogue into C
// MODE 1: A = Ain (x), epilogue scatters into g_q/g_k/g_v in [b][h][t][dh]
// 128x128 tile, 16-deep K slices, 256 threads, 8x8 per-thread microtile.
// ---------------------------------------------------------------------------
template<int MODE>
__global__ __launch_bounds__(256, 2)
void sgemm_k(const float* __restrict__ Ain, const float* __restrict__ Bw,
             const float* __restrict__ bias, float* __restrict__ C,
             int M, int N, int K) {
    __shared__ float As[2][16][132];   // transposed A tile: As[buf][kk][m]
    __shared__ float Bs[2][16][132];   // natural B tile:    Bs[buf][kk][n]

    const float* A = (MODE == 0) ? g_ctx : Ain;
    const int tid = threadIdx.x;
    const int tx = tid & 15, ty = tid >> 4;
    const int m0 = blockIdx.y * 128, n0 = blockIdx.x * 128;

    // per-thread load slots (fixed across slices)
    const int arow0 = (tid + 0) >> 2,        ac0 = ((tid + 0) & 3) * 4;
    const int arow1 = (tid + 256) >> 2,      ac1 = ((tid + 256) & 3) * 4;
    const int brow0 = (tid + 0) >> 5,        bc0 = ((tid + 0) & 31) * 4;
    const int brow1 = (tid + 256) >> 5,      bc1 = ((tid + 256) & 31) * 4;

    float acc[8][8];
    #pragma unroll
    for (int i = 0; i < 8; i++)
        #pragma unroll
        for (int j = 0; j < 8; j++) acc[i][j] = 0.f;

    // prefetch slice 0 into registers
    float4 pa0 = *reinterpret_cast<const float4*>(&A[(size_t)(m0 + arow0) * K + ac0]);
    float4 pa1 = *reinterpret_cast<const float4*>(&A[(size_t)(m0 + arow1) * K + ac1]);
    float4 pb0 = *reinterpret_cast<const float4*>(&Bw[(size_t)brow0 * N + n0 + bc0]);
    float4 pb1 = *reinterpret_cast<const float4*>(&Bw[(size_t)brow1 * N + n0 + bc1]);

    for (int k0 = 0; k0 < K; k0 += 16) {
        const int buf = (k0 >> 4) & 1;

        // store current slice from registers into this parity's buffer
        As[buf][ac0 + 0][arow0] = pa0.x; As[buf][ac0 + 1][arow0] = pa0.y;
        As[buf][ac0 + 2][arow0] = pa0.z; As[buf][ac0 + 3][arow0] = pa0.w;
        As[buf][ac1 + 0][arow1] = pa1.x; As[buf][ac1 + 1][arow1] = pa1.y;
        As[buf][ac1 + 2][arow1] = pa1.z; As[buf][ac1 + 3][arow1] = pa1.w;
        *reinterpret_cast<float4*>(&Bs[buf][brow0][bc0]) = pb0;
        *reinterpret_cast<float4*>(&Bs[buf][brow1][bc1]) = pb1;

        // issue next slice's global loads (in flight across the barrier)
        if (k0 + 16 < K) {
            pa0 = *reinterpret_cast<const float4*>(&A[(size_t)(m0 + arow0) * K + k0 + 16 + ac0]);
            pa1 = *reinterpret_cast<const float4*>(&A[(size_t)(m0 + arow1) * K + k0 + 16 + ac1]);
            pb0 = *reinterpret_cast<const float4*>(&Bw[(size_t)(k0 + 16 + brow0) * N + n0 + bc0]);
            pb1 = *reinterpret_cast<const float4*>(&Bw[(size_t)(k0 + 16 + brow1) * N + n0 + bc1]);
        }

        __syncthreads();   // the ONLY barrier per slice

        #pragma unroll
        for (int kk = 0; kk < 16; kk++) {
            float a[8], b[8];
            *reinterpret_cast<float4*>(&a[0]) = *reinterpret_cast<float4*>(&As[buf][kk][ty * 8]);
            *reinterpret_cast<float4*>(&a[4]) = *reinterpret_cast<float4*>(&As[buf][kk][ty * 8 + 4]);
            *reinterpret_cast<float4*>(&b[0]) = *reinterpret_cast<float4*>(&Bs[buf][kk][tx * 8]);
            *reinterpret_cast<float4*>(&b[4]) = *reinterpret_cast<float4*>(&Bs[buf][kk][tx * 8 + 4]);
            #pragma unroll
            for (int i = 0; i < 8; i++)
                #pragma unroll
                for (int j = 0; j < 8; j++) acc[i][j] += a[i] * b[j];
        }
    }

    if (MODE == 0) {
        #pragma unroll
        for (int i = 0; i < 8; i++) {
            int row = m0 + ty * 8 + i;
            #pragma unroll
            for (int j0 = 0; j0 < 8; j0 += 4) {
                int col = n0 + tx * 8 + j0;
                float4 v;
                v.x = acc[i][j0 + 0] + bias[col + 0];
                v.y = acc[i][j0 + 1] + bias[col + 1];
                v.z = acc[i][j0 + 2] + bias[col + 2];
                v.w = acc[i][j0 + 3] + bias[col + 3];
                *reinterpret_cast<float4*>(&C[(size_t)row * N + col]) = v;
            }
        }
    } else {
        #pragma unroll
        for (int i = 0; i < 8; i++) {
            int row = m0 + ty * 8 + i;
            int bb = row >> 11, t = row & 2047;
            #pragma unroll
            for (int j = 0; j < 8; j++) {
                int n = n0 + tx * 8 + j;
                int which = n >> 10;
                int rem = n & 1023;
                int h = rem >> 6, dh = rem & 63;
                float v = acc[i][j] + bias[n];
                float* dst = (which == 0) ? g_q : (which == 1) ? g_k : g_v;
                dst[(((size_t)(bb * HH + h)) * TT + t) * DH + dh] = v;
            }
        }
    }
}

// ---------------------------------------------------------------------------
// Attention: one block per (b, h, 16-query tile). Full 16x2048 score strip in
// smem -> exact softmax, weights written once, context from smem scores.
// (byte-identical to the R8 kernel that passed at 4103us)
// ---------------------------------------------------------------------------
#define SM_QS   0                       // [16][64]
#define SM_KT   1024                    // [64][128] swizzled float4 columns
#define SM_VB   (1024 + 8192)           // [128][68]
#define SM_SS   (1024 + 8192 + 8704)    // [16][2048]
#define ATTN_SMEM_FLOATS (1024 + 8192 + 8704 + 32768)
#define ATTN_SMEM_BYTES  (ATTN_SMEM_FLOATS * 4)   // 202752

__global__ __launch_bounds__(256)
void attn_kernel(float* __restrict__ wout) {
    extern __shared__ float sm[];
    float* qs = sm + SM_QS;
    float* kT = sm + SM_KT;
    float* vb = sm + SM_VB;
    float* sS = sm + SM_SS;

    const int tid = threadIdx.x;
    const int qt = blockIdx.x, h = blockIdx.y, b = blockIdx.z;
    const int q0 = qt * 16;
    const size_t hb = ((size_t)(b * HH + h)) * TT;

    // ---- load Q tile, pre-scaled by 1/sqrt(64) = 0.125 ----
    {
        int r = tid >> 4, c = (tid & 15) * 4;
        float4 v = *reinterpret_cast<const float4*>(&g_q[(hb + q0 + r) * DH + c]);
        qs[r * 64 + c + 0] = v.x * 0.125f;
        qs[r * 64 + c + 1] = v.y * 0.125f;
        qs[r * 64 + c + 2] = v.z * 0.125f;
        qs[r * 64 + c + 3] = v.w * 0.125f;
    }

    const int nch = (q0 + 16 + 127) >> 7;   // 128-key chunks covering causal span
    const int Lc = nch << 7;

    // ---- phase 1: scores -> sS (masked with -1e30) ----
    {
        const int rg = tid >> 5;     // 8 row groups of 2 rows
        const int cg = tid & 31;     // 32 col groups of 4 keys
        for (int c = 0; c < nch; c++) {
            const int kb = c << 7;
            __syncthreads();   // kT reuse safe / qs ready on first iter
            #pragma unroll
            for (int i = 0; i < 2; i++) {
                int gid = tid + i * 256;
                int kq = gid >> 4, c4 = gid & 15;
                float vr[4][4];
                #pragma unroll
                for (int jj = 0; jj < 4; jj++) {
                    float4 t4 = *reinterpret_cast<const float4*>(
                        &g_k[(hb + kb + kq * 4 + jj) * DH + c4 * 4]);
                    vr[jj][0] = t4.x; vr[jj][1] = t4.y;
                    vr[jj][2] = t4.z; vr[jj][3] = t4.w;
                }
                #pragma unroll
                for (int dd = 0; dd < 4; dd++) {
                    int row = c4 * 4 + dd;
                    int p = kq ^ (row & 31);
                    *reinterpret_cast<float4*>(&kT[row * 128 + p * 4]) =
                        make_float4(vr[0][dd], vr[1][dd], vr[2][dd], vr[3][dd]);
                }
            }
            __syncthreads();
            float acc[2][4];
            #pragma unroll
            for (int i = 0; i < 2; i++)
                #pragma unroll
                for (int j = 0; j < 4; j++) acc[i][j] = 0.f;
            #pragma unroll
            for (int kk = 0; kk < 64; kk++) {
                float qa = qs[(rg * 2 + 0) * 64 + kk];
                float qb = qs[(rg * 2 + 1) * 64 + kk];
                float4 kv = *reinterpret_cast<const float4*>(
                    &kT[kk * 128 + (cg ^ (kk & 31)) * 4]);
                acc[0][0] += qa * kv.x; acc[0][1] += qa * kv.y;
                acc[0][2] += qa * kv.z; acc[0][3] += qa * kv.w;
                acc[1][0] += qb * kv.x; acc[1][1] += qb * kv.y;
                acc[1][2] += qb * kv.z; acc[1][3] += qb * kv.w;
            }
            #pragma unroll
            for (int i = 0; i < 2; i++) {
                int row = rg * 2 + i;
                int qg = q0 + row;
                int kbase = kb + cg * 4;
                float4 o;
                o.x = (kbase + 0 <= qg) ? acc[i][0] : -1e30f;
                o.y = (kbase + 1 <= qg) ? acc[i][1] : -1e30f;
                o.z = (kbase + 2 <= qg) ? acc[i][2] : -1e30f;
                o.w = (kbase + 3 <= qg) ? acc[i][3] : -1e30f;
                *reinterpret_cast<float4*>(&sS[row * 2048 + kbase]) = o;
            }
        }
    }
    __syncthreads();

    // ---- phase 2: exact softmax, write weights (+ zero masked tail) ----
    {
        const int warp = tid >> 5, lane = tid & 31;
        for (int i = warp; i < 16; i += 8) {
            float* row = &sS[i * 2048];
            float mx = -1e30f;
            for (int j = lane; j < Lc; j += 32) mx = fmaxf(mx, row[j]);
            #pragma unroll
            for (int o = 16; o; o >>= 1) mx = fmaxf(mx, __shfl_xor_sync(0xffffffffu, mx, o));
            float s = 0.f;
            for (int j = lane; j < Lc; j += 32) {
                float e = __expf(row[j] - mx);
                row[j] = e; s += e;
            }
            #pragma unroll
            for (int o = 16; o; o >>= 1) s += __shfl_xor_sync(0xffffffffu, s, o);
            float inv = 1.0f / s;
            float* wr = &wout[(hb + q0 + i) * TT];
            for (int j = lane; j < Lc; j += 32) {
                float w = row[j] * inv;
                row[j] = w;
                wr[j] = w;
            }
            for (int j = Lc + lane; j < TT; j += 32) wr[j] = 0.f;
        }
    }
    __syncthreads();

    // ---- phase 3: context = W @ V ----
    {
        const int r = tid >> 4, dg = tid & 15;
        float a0 = 0.f, a1 = 0.f, a2 = 0.f, a3 = 0.f;
        for (int c = 0; c < nch; c++) {
            const int kb = c << 7;
            __syncthreads();   // vb reuse safe
            #pragma unroll
            for (int i = 0; i < 8; i++) {
                int idx = tid + i * 256;
                int key = idx >> 4, c4 = (idx & 15) * 4;
                *reinterpret_cast<float4*>(&vb[key * 68 + c4]) =
                    *reinterpret_cast<const float4*>(
                        &g_v[(hb + kb + key) * DH + c4]);
            }
            __syncthreads();
            #pragma unroll 4
            for (int j = 0; j < 128; j++) {
                float w = sS[r * 2048 + kb + j];
                float4 v4 = *reinterpret_cast<const float4*>(&vb[j * 68 + dg * 4]);
                a0 += w * v4.x; a1 += w * v4.y; a2 += w * v4.z; a3 += w * v4.w;
            }
        }
        *reinterpret_cast<float4*>(
            &g_ctx[((size_t)(b * TT + q0 + r)) * DD + h * 64 + dg * 4]) =
            make_float4(a0, a1, a2, a3);
    }
}

// ---------------------------------------------------------------------------
extern "C" void kernel_launch(void* const* d_in, const int* in_sizes, int n_in,
                              void* d_out, int out_size) {
    const float* x     = (const float*)d_in[0];
    const float* w_qkv = (const float*)d_in[1];
    const float* b_qkv = (const float*)d_in[2];
    const float* w_out = (const float*)d_in[3];
    const float* b_out = (const float*)d_in[4];
    float* out     = (float*)d_out;          // (B,T,D)
    float* weights = out + OUT0;             // (B,H,T,T)

    (void)in_sizes; (void)n_in; (void)out_size;

    cudaFuncSetAttribute(attn_kernel,
                         cudaFuncAttributeMaxDynamicSharedMemorySize,
                         ATTN_SMEM_BYTES);

    // 1) QKV projection, scattered into per-head Q/K/V layout
    sgemm_k<1><<<dim3(3 * DD / 128, MTOT / 128), 256>>>(
        x, w_qkv, b_qkv, nullptr, MTOT, 3 * DD, DD);

    // 2) causal attention: weights out + context
    attn_kernel<<<dim3(TT / 16, HH, BB), 256, ATTN_SMEM_BYTES>>>(weights);

    // 3) output projection
    sgemm_k<0><<<dim3(DD / 128, MTOT / 128), 256>>>(
        nullptr, w_out, b_out, out, MTOT, DD, DD);
}

// round 13
// speedup vs baseline: 3.8112x; 1.0933x over previous
#include <cuda_runtime.h>
#include <cuda_bf16.h>
#include <math.h>

#define BB 4
#define TT 2048
#define DD 1024
#define HH 16
#define DH 64
#define MTOT (BB*TT)            // 8192
#define OUT0 (BB*TT*DD)         // 8388608 floats: "out" part of d_out

// Scratch (static device arrays; runtime alloc forbidden)
__device__ float g_q[BB*HH*TT*DH];
__device__ float g_k[BB*HH*TT*DH];
__device__ float g_v[BB*HH*TT*DH];
__device__ float g_ctx[BB*TT*DD];

// ---------------------------------------------------------------------------
// SGEMM: C[M,N] = A[M,K] @ B[K,N] + bias     (R8: register-prefetch, 2-barrier)
// MODE 0: A = g_ctx, plain row-major epilogue into C
// MODE 1: A = Ain (x), epilogue scatters into g_q/g_k/g_v in [b][h][t][dh]
// ---------------------------------------------------------------------------
template<int MODE>
__global__ __launch_bounds__(256)
void sgemm_k(const float* __restrict__ Ain, const float* __restrict__ Bw,
             const float* __restrict__ bias, float* __restrict__ C,
             int M, int N, int K) {
    __shared__ float As[16][132];   // transposed A tile: As[kk][m]
    __shared__ float Bs[16][132];   // natural B tile:    Bs[kk][n]

    const float* A = (MODE == 0) ? g_ctx : Ain;
    const int tid = threadIdx.x;
    const int tx = tid & 15, ty = tid >> 4;
    const int m0 = blockIdx.y * 128, n0 = blockIdx.x * 128;

    const int arow0 = (tid + 0) >> 2,        ac0 = ((tid + 0) & 3) * 4;
    const int arow1 = (tid + 256) >> 2,      ac1 = ((tid + 256) & 3) * 4;
    const int brow0 = (tid + 0) >> 5,        bc0 = ((tid + 0) & 31) * 4;
    const int brow1 = (tid + 256) >> 5,      bc1 = ((tid + 256) & 31) * 4;

    float acc[8][8];
    #pragma unroll
    for (int i = 0; i < 8; i++)
        #pragma unroll
        for (int j = 0; j < 8; j++) acc[i][j] = 0.f;

    float4 pa0 = *reinterpret_cast<const float4*>(&A[(size_t)(m0 + arow0) * K + ac0]);
    float4 pa1 = *reinterpret_cast<const float4*>(&A[(size_t)(m0 + arow1) * K + ac1]);
    float4 pb0 = *reinterpret_cast<const float4*>(&Bw[(size_t)brow0 * N + n0 + bc0]);
    float4 pb1 = *reinterpret_cast<const float4*>(&Bw[(size_t)brow1 * N + n0 + bc1]);

    for (int k0 = 0; k0 < K; k0 += 16) {
        As[ac0 + 0][arow0] = pa0.x; As[ac0 + 1][arow0] = pa0.y;
        As[ac0 + 2][arow0] = pa0.z; As[ac0 + 3][arow0] = pa0.w;
        As[ac1 + 0][arow1] = pa1.x; As[ac1 + 1][arow1] = pa1.y;
        As[ac1 + 2][arow1] = pa1.z; As[ac1 + 3][arow1] = pa1.w;
        *reinterpret_cast<float4*>(&Bs[brow0][bc0]) = pb0;
        *reinterpret_cast<float4*>(&Bs[brow1][bc1]) = pb1;
        __syncthreads();

        if (k0 + 16 < K) {
            pa0 = *reinterpret_cast<const float4*>(&A[(size_t)(m0 + arow0) * K + k0 + 16 + ac0]);
            pa1 = *reinterpret_cast<const float4*>(&A[(size_t)(m0 + arow1) * K + k0 + 16 + ac1]);
            pb0 = *reinterpret_cast<const float4*>(&Bw[(size_t)(k0 + 16 + brow0) * N + n0 + bc0]);
            pb1 = *reinterpret_cast<const float4*>(&Bw[(size_t)(k0 + 16 + brow1) * N + n0 + bc1]);
        }

        #pragma unroll
        for (int kk = 0; kk < 16; kk++) {
            float a[8], b[8];
            *reinterpret_cast<float4*>(&a[0]) = *reinterpret_cast<float4*>(&As[kk][ty * 8]);
            *reinterpret_cast<float4*>(&a[4]) = *reinterpret_cast<float4*>(&As[kk][ty * 8 + 4]);
            *reinterpret_cast<float4*>(&b[0]) = *reinterpret_cast<float4*>(&Bs[kk][tx * 8]);
            *reinterpret_cast<float4*>(&b[4]) = *reinterpret_cast<float4*>(&Bs[kk][tx * 8 + 4]);
            #pragma unroll
            for (int i = 0; i < 8; i++)
                #pragma unroll
                for (int j = 0; j < 8; j++) acc[i][j] += a[i] * b[j];
        }
        __syncthreads();
    }

    if (MODE == 0) {
        #pragma unroll
        for (int i = 0; i < 8; i++) {
            int row = m0 + ty * 8 + i;
            #pragma unroll
            for (int j0 = 0; j0 < 8; j0 += 4) {
                int col = n0 + tx * 8 + j0;
                float4 v;
                v.x = acc[i][j0 + 0] + bias[col + 0];
                v.y = acc[i][j0 + 1] + bias[col + 1];
                v.z = acc[i][j0 + 2] + bias[col + 2];
                v.w = acc[i][j0 + 3] + bias[col + 3];
                *reinterpret_cast<float4*>(&C[(size_t)row * N + col]) = v;
            }
        }
    } else {
        #pragma unroll
        for (int i = 0; i < 8; i++) {
            int row = m0 + ty * 8 + i;
            int bb = row >> 11, t = row & 2047;
            #pragma unroll
            for (int j = 0; j < 8; j++) {
                int n = n0 + tx * 8 + j;
                int which = n >> 10;
                int rem = n & 1023;
                int h = rem >> 6, dh = rem & 63;
                float v = acc[i][j] + bias[n];
                float* dst = (which == 0) ? g_q : (which == 1) ? g_k : g_v;
                dst[(((size_t)(bb * HH + h)) * TT + t) * DH + dh] = v;
            }
        }
    }
}

// ---------------------------------------------------------------------------
// Attention: one block per (b, h, 16-query tile). Full 16x2048 score strip in
// smem -> exact softmax, weights written once, context from smem scores.
// P1: 4 rows x 2 keys per thread (halved kT crossbar traffic, conflict-free).
// P3: 4 rows x 1 col per thread (conflict-free scalar vb reads).
// Accumulation order per output element identical to R8 -> bit-identical out.
// ---------------------------------------------------------------------------
#define SM_QS   0                       // [16][64]
#define SM_KT   1024                    // [64][128] swizzled float4 columns
#define SM_VB   (1024 + 8192)           // [128][68]
#define SM_SS   (1024 + 8192 + 8704)    // [16][2048]
#define ATTN_SMEM_FLOATS (1024 + 8192 + 8704 + 32768)
#define ATTN_SMEM_BYTES  (ATTN_SMEM_FLOATS * 4)   // 202752

__global__ __launch_bounds__(256)
void attn_kernel(float* __restrict__ wout) {
    extern __shared__ float sm[];
    float* qs = sm + SM_QS;
    float* kT = sm + SM_KT;
    float* vb = sm + SM_VB;
    float* sS = sm + SM_SS;

    const int tid = threadIdx.x;
    const int qt = blockIdx.x, h = blockIdx.y, b = blockIdx.z;
    const int q0 = qt * 16;
    const size_t hb = ((size_t)(b * HH + h)) * TT;

    // ---- load Q tile, pre-scaled by 1/sqrt(64) = 0.125 ----
    {
        int r = tid >> 4, c = (tid & 15) * 4;
        float4 v = *reinterpret_cast<const float4*>(&g_q[(hb + q0 + r) * DH + c]);
        qs[r * 64 + c + 0] = v.x * 0.125f;
        qs[r * 64 + c + 1] = v.y * 0.125f;
        qs[r * 64 + c + 2] = v.z * 0.125f;
        qs[r * 64 + c + 3] = v.w * 0.125f;
    }

    const int nch = (q0 + 16 + 127) >> 7;   // 128-key chunks covering causal span
    const int Lc = nch << 7;

    // ---- phase 1: scores -> sS (masked with -1e30) ----
    {
        const int rg4 = tid >> 6;    // 4 row groups of 4 rows (uniform per warp)
        const int cg2 = tid & 63;    // 64 col groups of 2 keys
        const int kq = cg2 >> 1, half2 = (cg2 & 1) * 2;
        for (int c = 0; c < nch; c++) {
            const int kb = c << 7;
            __syncthreads();   // kT reuse safe / qs ready on first iter
            #pragma unroll
            for (int i = 0; i < 2; i++) {
                int gid = tid + i * 256;
                int kq2 = gid >> 4, c4 = gid & 15;
                float vr[4][4];
                #pragma unroll
                for (int jj = 0; jj < 4; jj++) {
                    float4 t4 = *reinterpret_cast<const float4*>(
                        &g_k[(hb + kb + kq2 * 4 + jj) * DH + c4 * 4]);
                    vr[jj][0] = t4.x; vr[jj][1] = t4.y;
                    vr[jj][2] = t4.z; vr[jj][3] = t4.w;
                }
                #pragma unroll
                for (int dd = 0; dd < 4; dd++) {
                    int row = c4 * 4 + dd;
                    int p = kq2 ^ (row & 31);
                    *reinterpret_cast<float4*>(&kT[row * 128 + p * 4]) =
                        make_float4(vr[0][dd], vr[1][dd], vr[2][dd], vr[3][dd]);
                }
            }
            __syncthreads();
            float acc[4][2];
            #pragma unroll
            for (int i = 0; i < 4; i++) { acc[i][0] = 0.f; acc[i][1] = 0.f; }
            #pragma unroll
            for (int kk = 0; kk < 64; kk++) {
                float qv[4];
                #pragma unroll
                for (int i = 0; i < 4; i++)
                    qv[i] = qs[(rg4 * 4 + i) * 64 + kk];
                float2 kv = *reinterpret_cast<const float2*>(
                    &kT[kk * 128 + ((kq ^ (kk & 31)) << 2) + half2]);
                #pragma unroll
                for (int i = 0; i < 4; i++) {
                    acc[i][0] += qv[i] * kv.x;
                    acc[i][1] += qv[i] * kv.y;
                }
            }
            #pragma unroll
            for (int i = 0; i < 4; i++) {
                int row = rg4 * 4 + i;
                int qg = q0 + row;
                int kbase = kb + cg2 * 2;
                float2 o;
                o.x = (kbase + 0 <= qg) ? acc[i][0] : -1e30f;
                o.y = (kbase + 1 <= qg) ? acc[i][1] : -1e30f;
                *reinterpret_cast<float2*>(&sS[row * 2048 + kbase]) = o;
            }
        }
    }
    __syncthreads();

    // ---- phase 2: exact softmax, write weights (+ zero masked tail) ----
    {
        const int warp = tid >> 5, lane = tid & 31;
        for (int i = warp; i < 16; i += 8) {
            float* row = &sS[i * 2048];
            float mx = -1e30f;
            for (int j = lane; j < Lc; j += 32) mx = fmaxf(mx, row[j]);
            #pragma unroll
            for (int o = 16; o; o >>= 1) mx = fmaxf(mx, __shfl_xor_sync(0xffffffffu, mx, o));
            float s = 0.f;
            for (int j = lane; j < Lc; j += 32) {
                float e = __expf(row[j] - mx);
                row[j] = e; s += e;
            }
            #pragma unroll
            for (int o = 16; o; o >>= 1) s += __shfl_xor_sync(0xffffffffu, s, o);
            float inv = 1.0f / s;
            float* wr = &wout[(hb + q0 + i) * TT];
            for (int j = lane; j < Lc; j += 32) {
                float w = row[j] * inv;
                row[j] = w;
                wr[j] = w;
            }
            for (int j = Lc + lane; j < TT; j += 32) wr[j] = 0.f;
        }
    }
    __syncthreads();

    // ---- phase 3: context = W @ V  (4 rows x 1 col per thread) ----
    {
        const int r2 = tid >> 6;    // 4 row groups of 4 rows (uniform per warp)
        const int c3 = tid & 63;    // 64 columns
        float a[4] = {0.f, 0.f, 0.f, 0.f};
        for (int c = 0; c < nch; c++) {
            const int kb = c << 7;
            __syncthreads();   // vb reuse safe
            #pragma unroll
            for (int i = 0; i < 8; i++) {
                int idx = tid + i * 256;
                int key = idx >> 4, c4 = (idx & 15) * 4;
                *reinterpret_cast<float4*>(&vb[key * 68 + c4]) =
                    *reinterpret_cast<const float4*>(
                        &g_v[(hb + kb + key) * DH + c4]);
            }
            __syncthreads();
            #pragma unroll 4
            for (int j = 0; j < 128; j++) {
                float vv = vb[j * 68 + c3];
                #pragma unroll
                for (int i = 0; i < 4; i++)
                    a[i] += sS[(r2 * 4 + i) * 2048 + kb + j] * vv;
            }
        }
        #pragma unroll
        for (int i = 0; i < 4; i++)
            g_ctx[((size_t)(b * TT + q0 + r2 * 4 + i)) * DD + h * 64 + c3] = a[i];
    }
}

// ---------------------------------------------------------------------------
extern "C" void kernel_launch(void* const* d_in, const int* in_sizes, int n_in,
                              void* d_out, int out_size) {
    const float* x     = (const float*)d_in[0];
    const float* w_qkv = (const float*)d_in[1];
    const float* b_qkv = (const float*)d_in[2];
    const float* w_out = (const float*)d_in[3];
    const float* b_out = (const float*)d_in[4];
    float* out     = (float*)d_out;          // (B,T,D)
    float* weights = out + OUT0;             // (B,H,T,T)

    (void)in_sizes; (void)n_in; (void)out_size;

    cudaFuncSetAttribute(attn_kernel,
                         cudaFuncAttributeMaxDynamicSharedMemorySize,
                         ATTN_SMEM_BYTES);

    // 1) QKV projection, scattered into per-head Q/K/V layout
    sgemm_k<1><<<dim3(3 * DD / 128, MTOT / 128), 256>>>(
        x, w_qkv, b_qkv, nullptr, MTOT, 3 * DD, DD);

    // 2) causal attention: weights out + context
    attn_kernel<<<dim3(TT / 16, HH, BB), 256, ATTN_SMEM_BYTES>>>(weights);

    // 3) output projection
    sgemm_k<0><<<dim3(DD / 128, MTOT / 128), 256>>>(
        nullptr, w_out, b_out, out, MTOT, DD, DD);
}

// round 14
// speedup vs baseline: 4.0152x; 1.0535x over previous
#include <cuda_runtime.h>
#include <cuda_bf16.h>
#include <math.h>

#define BB 4
#define TT 2048
#define DD 1024
#define HH 16
#define DH 64
#define MTOT (BB*TT)            // 8192
#define OUT0 (BB*TT*DD)         // 8388608 floats: "out" part of d_out

// Scratch (static device arrays; runtime alloc forbidden)
__device__ float g_q[BB*HH*TT*DH];
__device__ float g_k[BB*HH*TT*DH];
__device__ float g_v[BB*HH*TT*DH];
__device__ float g_ctx[BB*TT*DD];

// ---------------------------------------------------------------------------
// SGEMM: C[M,N] = A[M,K] @ B[K,N] + bias     (R8: register-prefetch, 2-barrier)
// MODE 0: A = g_ctx, plain row-major epilogue into C
// MODE 1: A = Ain (x), epilogue scatters into g_q/g_k/g_v in [b][h][t][dh]
// ---------------------------------------------------------------------------
template<int MODE>
__global__ __launch_bounds__(256)
void sgemm_k(const float* __restrict__ Ain, const float* __restrict__ Bw,
             const float* __restrict__ bias, float* __restrict__ C,
             int M, int N, int K) {
    __shared__ float As[16][132];   // transposed A tile: As[kk][m]
    __shared__ float Bs[16][132];   // natural B tile:    Bs[kk][n]

    const float* A = (MODE == 0) ? g_ctx : Ain;
    const int tid = threadIdx.x;
    const int tx = tid & 15, ty = tid >> 4;
    const int m0 = blockIdx.y * 128, n0 = blockIdx.x * 128;

    const int arow0 = (tid + 0) >> 2,        ac0 = ((tid + 0) & 3) * 4;
    const int arow1 = (tid + 256) >> 2,      ac1 = ((tid + 256) & 3) * 4;
    const int brow0 = (tid + 0) >> 5,        bc0 = ((tid + 0) & 31) * 4;
    const int brow1 = (tid + 256) >> 5,      bc1 = ((tid + 256) & 31) * 4;

    float acc[8][8];
    #pragma unroll
    for (int i = 0; i < 8; i++)
        #pragma unroll
        for (int j = 0; j < 8; j++) acc[i][j] = 0.f;

    float4 pa0 = *reinterpret_cast<const float4*>(&A[(size_t)(m0 + arow0) * K + ac0]);
    float4 pa1 = *reinterpret_cast<const float4*>(&A[(size_t)(m0 + arow1) * K + ac1]);
    float4 pb0 = *reinterpret_cast<const float4*>(&Bw[(size_t)brow0 * N + n0 + bc0]);
    float4 pb1 = *reinterpret_cast<const float4*>(&Bw[(size_t)brow1 * N + n0 + bc1]);

    for (int k0 = 0; k0 < K; k0 += 16) {
        As[ac0 + 0][arow0] = pa0.x; As[ac0 + 1][arow0] = pa0.y;
        As[ac0 + 2][arow0] = pa0.z; As[ac0 + 3][arow0] = pa0.w;
        As[ac1 + 0][arow1] = pa1.x; As[ac1 + 1][arow1] = pa1.y;
        As[ac1 + 2][arow1] = pa1.z; As[ac1 + 3][arow1] = pa1.w;
        *reinterpret_cast<float4*>(&Bs[brow0][bc0]) = pb0;
        *reinterpret_cast<float4*>(&Bs[brow1][bc1]) = pb1;
        __syncthreads();

        if (k0 + 16 < K) {
            pa0 = *reinterpret_cast<const float4*>(&A[(size_t)(m0 + arow0) * K + k0 + 16 + ac0]);
            pa1 = *reinterpret_cast<const float4*>(&A[(size_t)(m0 + arow1) * K + k0 + 16 + ac1]);
            pb0 = *reinterpret_cast<const float4*>(&Bw[(size_t)(k0 + 16 + brow0) * N + n0 + bc0]);
            pb1 = *reinterpret_cast<const float4*>(&Bw[(size_t)(k0 + 16 + brow1) * N + n0 + bc1]);
        }

        #pragma unroll
        for (int kk = 0; kk < 16; kk++) {
            float a[8], b[8];
            *reinterpret_cast<float4*>(&a[0]) = *reinterpret_cast<float4*>(&As[kk][ty * 8]);
            *reinterpret_cast<float4*>(&a[4]) = *reinterpret_cast<float4*>(&As[kk][ty * 8 + 4]);
            *reinterpret_cast<float4*>(&b[0]) = *reinterpret_cast<float4*>(&Bs[kk][tx * 8]);
            *reinterpret_cast<float4*>(&b[4]) = *reinterpret_cast<float4*>(&Bs[kk][tx * 8 + 4]);
            #pragma unroll
            for (int i = 0; i < 8; i++)
                #pragma unroll
                for (int j = 0; j < 8; j++) acc[i][j] += a[i] * b[j];
        }
        __syncthreads();
    }

    if (MODE == 0) {
        #pragma unroll
        for (int i = 0; i < 8; i++) {
            int row = m0 + ty * 8 + i;
            #pragma unroll
            for (int j0 = 0; j0 < 8; j0 += 4) {
                int col = n0 + tx * 8 + j0;
                float4 v;
                v.x = acc[i][j0 + 0] + bias[col + 0];
                v.y = acc[i][j0 + 1] + bias[col + 1];
                v.z = acc[i][j0 + 2] + bias[col + 2];
                v.w = acc[i][j0 + 3] + bias[col + 3];
                *reinterpret_cast<float4*>(&C[(size_t)row * N + col]) = v;
            }
        }
    } else {
        #pragma unroll
        for (int i = 0; i < 8; i++) {
            int row = m0 + ty * 8 + i;
            int bb = row >> 11, t = row & 2047;
            #pragma unroll
            for (int j = 0; j < 8; j++) {
                int n = n0 + tx * 8 + j;
                int which = n >> 10;
                int rem = n & 1023;
                int h = rem >> 6, dh = rem & 63;
                float v = acc[i][j] + bias[n];
                float* dst = (which == 0) ? g_q : (which == 1) ? g_k : g_v;
                dst[(((size_t)(bb * HH + h)) * TT + t) * DH + dh] = v;
            }
        }
    }
}

// ---------------------------------------------------------------------------
// Attention: one block per (b, h, 16-query tile). Full 16x2048 score strip in
// smem -> exact softmax, weights written once, context from smem scores.
// P1: 4 rows x 2 keys per thread; q hoisted as float4 per 4 kk.
// P3: 4 rows x 1 col per thread; weights hoisted as float4 per 4 j.
// Accumulation order per output element identical to R13 -> bit-identical out.
// ---------------------------------------------------------------------------
#define SM_QS   0                       // [16][64]
#define SM_KT   1024                    // [64][128] swizzled float4 columns
#define SM_VB   (1024 + 8192)           // [128][68]
#define SM_SS   (1024 + 8192 + 8704)    // [16][2048]
#define ATTN_SMEM_FLOATS (1024 + 8192 + 8704 + 32768)
#define ATTN_SMEM_BYTES  (ATTN_SMEM_FLOATS * 4)   // 202752

__global__ __launch_bounds__(256)
void attn_kernel(float* __restrict__ wout) {
    extern __shared__ float sm[];
    float* qs = sm + SM_QS;
    float* kT = sm + SM_KT;
    float* vb = sm + SM_VB;
    float* sS = sm + SM_SS;

    const int tid = threadIdx.x;
    const int qt = blockIdx.x, h = blockIdx.y, b = blockIdx.z;
    const int q0 = qt * 16;
    const size_t hb = ((size_t)(b * HH + h)) * TT;

    // ---- load Q tile, pre-scaled by 1/sqrt(64) = 0.125 ----
    {
        int r = tid >> 4, c = (tid & 15) * 4;
        float4 v = *reinterpret_cast<const float4*>(&g_q[(hb + q0 + r) * DH + c]);
        qs[r * 64 + c + 0] = v.x * 0.125f;
        qs[r * 64 + c + 1] = v.y * 0.125f;
        qs[r * 64 + c + 2] = v.z * 0.125f;
        qs[r * 64 + c + 3] = v.w * 0.125f;
    }

    const int nch = (q0 + 16 + 127) >> 7;   // 128-key chunks covering causal span
    const int Lc = nch << 7;

    // ---- phase 1: scores -> sS (masked with -1e30) ----
    {
        const int rg4 = tid >> 6;    // 4 row groups of 4 rows (uniform per warp)
        const int cg2 = tid & 63;    // 64 col groups of 2 keys
        const int kq = cg2 >> 1, half2 = (cg2 & 1) * 2;
        for (int c = 0; c < nch; c++) {
            const int kb = c << 7;
            __syncthreads();   // kT reuse safe / qs ready on first iter
            #pragma unroll
            for (int i = 0; i < 2; i++) {
                int gid = tid + i * 256;
                int kq2 = gid >> 4, c4 = gid & 15;
                float vr[4][4];
                #pragma unroll
                for (int jj = 0; jj < 4; jj++) {
                    float4 t4 = *reinterpret_cast<const float4*>(
                        &g_k[(hb + kb + kq2 * 4 + jj) * DH + c4 * 4]);
                    vr[jj][0] = t4.x; vr[jj][1] = t4.y;
                    vr[jj][2] = t4.z; vr[jj][3] = t4.w;
                }
                #pragma unroll
                for (int dd = 0; dd < 4; dd++) {
                    int row = c4 * 4 + dd;
                    int p = kq2 ^ (row & 31);
                    *reinterpret_cast<float4*>(&kT[row * 128 + p * 4]) =
                        make_float4(vr[0][dd], vr[1][dd], vr[2][dd], vr[3][dd]);
                }
            }
            __syncthreads();
            float acc[4][2];
            #pragma unroll
            for (int i = 0; i < 4; i++) { acc[i][0] = 0.f; acc[i][1] = 0.f; }
            #pragma unroll
            for (int kk = 0; kk < 64; kk += 4) {
                float4 qv4[4];
                #pragma unroll
                for (int i = 0; i < 4; i++)
                    qv4[i] = *reinterpret_cast<const float4*>(
                        &qs[(rg4 * 4 + i) * 64 + kk]);
                #pragma unroll
                for (int u = 0; u < 4; u++) {
                    const int k2 = kk + u;
                    float2 kv = *reinterpret_cast<const float2*>(
                        &kT[k2 * 128 + ((kq ^ (k2 & 31)) << 2) + half2]);
                    #pragma unroll
                    for (int i = 0; i < 4; i++) {
                        float qv = (u == 0) ? qv4[i].x : (u == 1) ? qv4[i].y
                                 : (u == 2) ? qv4[i].z : qv4[i].w;
                        acc[i][0] += qv * kv.x;
                        acc[i][1] += qv * kv.y;
                    }
                }
            }
            #pragma unroll
            for (int i = 0; i < 4; i++) {
                int row = rg4 * 4 + i;
                int qg = q0 + row;
                int kbase = kb + cg2 * 2;
                float2 o;
                o.x = (kbase + 0 <= qg) ? acc[i][0] : -1e30f;
                o.y = (kbase + 1 <= qg) ? acc[i][1] : -1e30f;
                *reinterpret_cast<float2*>(&sS[row * 2048 + kbase]) = o;
            }
        }
    }
    __syncthreads();

    // ---- phase 2: exact softmax, write weights (+ zero masked tail) ----
    {
        const int warp = tid >> 5, lane = tid & 31;
        for (int i = warp; i < 16; i += 8) {
            float* row = &sS[i * 2048];
            float mx = -1e30f;
            for (int j = lane; j < Lc; j += 32) mx = fmaxf(mx, row[j]);
            #pragma unroll
            for (int o = 16; o; o >>= 1) mx = fmaxf(mx, __shfl_xor_sync(0xffffffffu, mx, o));
            float s = 0.f;
            for (int j = lane; j < Lc; j += 32) {
                float e = __expf(row[j] - mx);
                row[j] = e; s += e;
            }
            #pragma unroll
            for (int o = 16; o; o >>= 1) s += __shfl_xor_sync(0xffffffffu, s, o);
            float inv = 1.0f / s;
            float* wr = &wout[(hb + q0 + i) * TT];
            for (int j = lane; j < Lc; j += 32) {
                float w = row[j] * inv;
                row[j] = w;
                wr[j] = w;
            }
            for (int j = Lc + lane; j < TT; j += 32) wr[j] = 0.f;
        }
    }
    __syncthreads();

    // ---- phase 3: context = W @ V  (4 rows x 1 col; w hoisted as float4) ----
    {
        const int r2 = tid >> 6;    // 4 row groups of 4 rows (uniform per warp)
        const int c3 = tid & 63;    // 64 columns
        float a[4] = {0.f, 0.f, 0.f, 0.f};
        for (int c = 0; c < nch; c++) {
            const int kb = c << 7;
            __syncthreads();   // vb reuse safe
            #pragma unroll
            for (int i = 0; i < 8; i++) {
                int idx = tid + i * 256;
                int key = idx >> 4, c4 = (idx & 15) * 4;
                *reinterpret_cast<float4*>(&vb[key * 68 + c4]) =
                    *reinterpret_cast<const float4*>(
                        &g_v[(hb + kb + key) * DH + c4]);
            }
            __syncthreads();
            #pragma unroll 2
            for (int j = 0; j < 128; j += 4) {
                float4 w4[4];
                #pragma unroll
                for (int i = 0; i < 4; i++)
                    w4[i] = *reinterpret_cast<const float4*>(
                        &sS[(r2 * 4 + i) * 2048 + kb + j]);
                #pragma unroll
                for (int u = 0; u < 4; u++) {
                    float vv = vb[(j + u) * 68 + c3];
                    #pragma unroll
                    for (int i = 0; i < 4; i++) {
                        float wv = (u == 0) ? w4[i].x : (u == 1) ? w4[i].y
                                 : (u == 2) ? w4[i].z : w4[i].w;
                        a[i] += wv * vv;
                    }
                }
            }
        }
        #pragma unroll
        for (int i = 0; i < 4; i++)
            g_ctx[((size_t)(b * TT + q0 + r2 * 4 + i)) * DD + h * 64 + c3] = a[i];
    }
}

// ---------------------------------------------------------------------------
extern "C" void kernel_launch(void* const* d_in, const int* in_sizes, int n_in,
                              void* d_out, int out_size) {
    const float* x     = (const float*)d_in[0];
    const float* w_qkv = (const float*)d_in[1];
    const float* b_qkv = (const float*)d_in[2];
    const float* w_out = (const float*)d_in[3];
    const float* b_out = (const float*)d_in[4];
    float* out     = (float*)d_out;          // (B,T,D)
    float* weights = out + OUT0;             // (B,H,T,T)

    (void)in_sizes; (void)n_in; (void)out_size;

    cudaFuncSetAttribute(attn_kernel,
                         cudaFuncAttributeMaxDynamicSharedMemorySize,
                         ATTN_SMEM_BYTES);

    // 1) QKV projection, scattered into per-head Q/K/V layout
    sgemm_k<1><<<dim3(3 * DD / 128, MTOT / 128), 256>>>(
        x, w_qkv, b_qkv, nullptr, MTOT, 3 * DD, DD);

    // 2) causal attention: weights out + context
    attn_kernel<<<dim3(TT / 16, HH, BB), 256, ATTN_SMEM_BYTES>>>(weights);

    // 3) output projection
    sgemm_k<0><<<dim3(DD / 128, MTOT / 128), 256>>>(
        nullptr, w_out, b_out, out, MTOT, DD, DD);
}